// round 4
// baseline (speedup 1.0000x reference)
#include <cuda_runtime.h>
#include <cuda_bf16.h>

// LocalPatternExtractor: binary-weight dw-conv -> binary pw-conv -> BN -> 4-step
// quantized LIF. Forward-value analysis: the POT quantizer clips the membrane
// potential to <= 127/128 < THRESHOLD(=1.0), and the spike is the hard
// comparison (mem >= THRESHOLD) on the quantized mem (surrogate is forward-
// canceled by the STE). Hence no spike ever fires: out == 0 everywhere and
// reg_loss == 0. The kernel's only job is to write out_size float zeros
// (d_out is poisoned to 0xAA by the harness).

__global__ void lpe_zero_vec4(float4* __restrict__ out4, long long n4) {
    long long i = (long long)blockIdx.x * blockDim.x + threadIdx.x;
    if (i < n4) {
        out4[i] = make_float4(0.f, 0.f, 0.f, 0.f);
    }
}

__global__ void lpe_zero_tail(float* __restrict__ out, long long start, long long n) {
    long long i = start + (long long)blockIdx.x * blockDim.x + threadIdx.x;
    if (i < n) {
        out[i] = 0.f;
    }
}

extern "C" void kernel_launch(void* const* d_in, const int* in_sizes, int n_in,
                              void* d_out, int out_size) {
    (void)d_in; (void)in_sizes; (void)n_in;

    long long n  = (long long)out_size;   // 16*256*5000 + 1 = 20,480,001 floats
    long long n4 = n >> 2;                // float4 chunks (d_out is 256B-aligned)

    if (n4 > 0) {
        const int threads = 256;
        long long blocks = (n4 + threads - 1) / threads;
        lpe_zero_vec4<<<(unsigned)blocks, threads>>>((float4*)d_out, n4);
    }

    long long tail = n - (n4 << 2);
    if (tail > 0) {
        lpe_zero_tail<<<1, 32>>>((float*)d_out, n4 << 2, n);
    }
}

// round 7
// speedup vs baseline: 1.1382x; 1.1382x over previous
#include <cuda_runtime.h>
#include <cuda_bf16.h>

// LocalPatternExtractor: binary-weight dw-conv -> binary pw-conv -> BN -> 4-step
// quantized LIF. Forward-value analysis: quantize_pot_ste clips the membrane
// potential to round(v/step) in [-128,127] with step = 1/128, so the quantized
// mem is <= 127/128 < THRESHOLD = 1.0. The spike forward value is the hard
// comparison (mem >= THRESHOLD) on that quantized mem (the sigmoid surrogate is
// forward-canceled by the stop_gradient STE). Hence no spike ever fires:
// out == 0 everywhere and reg_loss = 0.01 * mean(0) = 0. The kernel's only job
// is to write out_size float zeros over the 0xAA-poisoned d_out.
//
// R4: fuse the 1-element tail into the main vec4 kernel — the separate tail
// launch was a serialized 3.36us graph node (20% of runtime) to write 4 bytes.

__global__ void lpe_zero_fused(float* __restrict__ out, long long n) {
    long long i4 = ((long long)blockIdx.x * blockDim.x + threadIdx.x) << 2;
    if (i4 + 3 < n) {
        // full float4 store (d_out is 256B-aligned from the harness allocation)
        *reinterpret_cast<float4*>(out + i4) = make_float4(0.f, 0.f, 0.f, 0.f);
    } else if (i4 < n) {
        // straddling thread: scalar tail (at most 3 elements)
        for (long long j = i4; j < n; ++j) out[j] = 0.f;
    }
}

extern "C" void kernel_launch(void* const* d_in, const int* in_sizes, int n_in,
                              void* d_out, int out_size) {
    (void)d_in; (void)in_sizes; (void)n_in;

    long long n = (long long)out_size;            // 16*256*5000 + 1 = 20,480,001
    long long nthreads = (n + 3) >> 2;            // one float4 (or tail) per thread
    const int threads = 256;
    long long blocks = (nthreads + threads - 1) / threads;

    lpe_zero_fused<<<(unsigned)blocks, threads>>>((float*)d_out, n);
}